// round 2
// baseline (speedup 1.0000x reference)
#include <cuda_runtime.h>
#include <cstdint>

// Problem constants (shapes are fixed by the dataset)
#define B_    2048
#define F_    512
#define H_    64
#define K_    8
#define D_    128
#define ASR_  128
#define MM_   768
#define OUT_  256
#define ZPRE_ (ASR_ + MM_)          // 896
#define ZK_   (ZPRE_ + F_ * K_)     // 4992 (virtual contraction dim)
#define KHALF (ZK_ / 2)             // 2496 (split-K)
#define PROJ_IN_ (ASR_ + MM_ + F_ * D_)   // 66432

typedef unsigned long long ull;

// ---------- packed f32x2 helpers (Blackwell FFMA2) ----------
__device__ __forceinline__ ull pack2(float lo, float hi) {
    ull r; asm("mov.b64 %0, {%1, %2};" : "=l"(r) : "f"(lo), "f"(hi)); return r;
}
__device__ __forceinline__ void unpack2(ull v, float& lo, float& hi) {
    asm("mov.b64 {%0, %1}, %2;" : "=f"(lo), "=f"(hi) : "l"(v));
}
__device__ __forceinline__ void ffma2(ull& c, ull a, ull b) {
    asm("fma.rn.f32x2 %0, %1, %2, %0;" : "+l"(c) : "l"(a), "l"(b));
}

// ---------- device scratch (no allocation allowed) ----------
__device__ float g_P[(size_t)B_ * (F_ * K_)];       // 2048 x 4096   (32 MB)
__device__ float g_Bmat[(size_t)ZK_ * OUT_];        // 4992 x 256    (5 MB)
__device__ float g_CP[2 * (size_t)B_ * OUT_];       // split-K partials (4 MB)

// ============================================================
// Kernel A: sanitize + per-feature MLP + leaky + softmax -> P
// grid = F_ blocks, 256 threads; each thread handles 8 batch rows.
// ============================================================
__global__ __launch_bounds__(256) void kernelA(
    const float* __restrict__ stat, const float* __restrict__ w1,
    const float* __restrict__ b1,   const float* __restrict__ w2,
    const float* __restrict__ b2,   const float* __restrict__ tau)
{
    __shared__ float w1s[H_], b1s[H_], b2s[K_], taus[K_];
    __shared__ ull   w2s[H_ * K_ / 2];    // [64][8] floats viewed as [64][4] f32x2

    const int f = blockIdx.x;
    const int tid = threadIdx.x;

    if (tid < H_) {
        const float* p = w1 + (size_t)f * 3 * H_;
        w1s[tid] = p[tid] + p[H_ + tid] + p[2 * H_ + tid];   // sum over 3 identical copies
        b1s[tid] = b1[(size_t)f * H_ + tid];
    } else if (tid < H_ + K_) {
        b2s[tid - H_] = b2[(size_t)f * K_ + tid - H_];
        taus[tid - H_] = tau[(size_t)f * K_ + tid - H_];
    }
    if (tid < 128) ((float4*)w2s)[tid] = ((const float4*)(w2 + (size_t)f * H_ * K_))[tid];
    __syncthreads();

    float x[8];
#pragma unroll
    for (int i = 0; i < 8; i++) {
        float v = stat[(size_t)(i * 256 + tid) * F_ + f];
        x[i] = (v >= 0.f) ? v : 0.f;           // NaN and negatives -> 0
    }

    ull acc[8][4];
#pragma unroll
    for (int i = 0; i < 8; i++)
#pragma unroll
        for (int k = 0; k < 4; k++) acc[i][k] = 0ull;

#pragma unroll 4
    for (int j = 0; j < H_; j++) {
        const float wj = w1s[j];
        const float bj = b1s[j];
        const ull u0 = w2s[j * 4 + 0];
        const ull u1 = w2s[j * 4 + 1];
        const ull u2 = w2s[j * 4 + 2];
        const ull u3 = w2s[j * 4 + 3];
#pragma unroll
        for (int i = 0; i < 8; i++) {
            float h = fmaf(x[i], wj, bj);
            h = fmaxf(h, 0.01f * h);           // leaky relu
            ull h2 = pack2(h, h);
            ffma2(acc[i][0], h2, u0);
            ffma2(acc[i][1], h2, u1);
            ffma2(acc[i][2], h2, u2);
            ffma2(acc[i][3], h2, u3);
        }
    }

#pragma unroll
    for (int i = 0; i < 8; i++) {
        float s[8];
#pragma unroll
        for (int k = 0; k < 4; k++) unpack2(acc[i][k], s[2 * k], s[2 * k + 1]);
        float mx = -3.0e38f;
#pragma unroll
        for (int k = 0; k < K_; k++) {
            float pre = s[k] + b2s[k];
            pre = fmaxf(pre, 0.01f * pre);     // leaky relu
            pre *= taus[k];                    // tau scale
            s[k] = pre;
            mx = fmaxf(mx, pre);
        }
        float sum = 0.f;
#pragma unroll
        for (int k = 0; k < K_; k++) { s[k] = __expf(s[k] - mx); sum += s[k]; }
        const float inv = __frcp_rn(sum);
        float4 o0 = make_float4(s[0] * inv, s[1] * inv, s[2] * inv, s[3] * inv);
        float4 o1 = make_float4(s[4] * inv, s[5] * inv, s[6] * inv, s[7] * inv);
        float4* dst = (float4*)(g_P + (size_t)(i * 256 + tid) * (F_ * K_) + f * K_);
        dst[0] = o0; dst[1] = o1;
    }
}

// ============================================================
// Kernel B: build Bmat[4992][256].
//   rows 0..895:   W^T  (Bmat[i][o] = proj_w[o][i])
//   rows 896..:    M[f*8+k][o] = sum_d emb[f,k,d] * proj_w[o, 896+f*128+d]
// grid = 512 + 28 blocks, 256 threads.
// ============================================================
__global__ __launch_bounds__(256) void kernelB(
    const float* __restrict__ emb, const float* __restrict__ pw)
{
    const int blk = blockIdx.x;
    const int tid = threadIdx.x;
    if (blk < F_) {
        __shared__ float es[K_][D_];           // 4 KB
        const int f = blk;
        ((float4*)es)[tid] = ((const float4*)(emb + (size_t)f * K_ * D_))[tid];
        __syncthreads();
        const int w = tid >> 5, l = tid & 31;
        const float* base = pw + ZPRE_ + (size_t)f * D_;
        for (int oi = 0; oi < 32; oi++) {
            const int o = w * 32 + oi;
            float4 wv = *(const float4*)(base + (size_t)o * PROJ_IN_ + l * 4);
            float acc[K_];
#pragma unroll
            for (int k = 0; k < K_; k++) {
                float4 e4 = *(const float4*)&es[k][l * 4];
                acc[k] = wv.x * e4.x + wv.y * e4.y + wv.z * e4.z + wv.w * e4.w;
            }
#pragma unroll
            for (int off = 16; off > 0; off >>= 1)
#pragma unroll
                for (int k = 0; k < K_; k++)
                    acc[k] += __shfl_xor_sync(0xffffffff, acc[k], off);
            if (l == 0) {
#pragma unroll
                for (int k = 0; k < K_; k++)
                    g_Bmat[(size_t)(ZPRE_ + f * K_ + k) * OUT_ + o] = acc[k];
            }
        }
    } else {
        // transpose W[:, 0:896] into Bmat[0:896][:]
        const int i0 = (blk - F_) * 32;        // 28 blocks * 32 = 896
        const int o = tid;
        for (int ii = 0; ii < 32; ii++)
            g_Bmat[(size_t)(i0 + ii) * OUT_ + o] = pw[(size_t)o * PROJ_IN_ + i0 + ii];
    }
}

// ============================================================
// Kernel C: split-K SGEMM.  CP[z] += Z[2048 x 2496] @ Bmat-half
// Z is virtual: [asr | mm | P].  BM=64 BN=64 BK=16, 128 threads,
// thread tile 8(m) x 4(n) with f32x2 accumulators (m-paired).
// grid = (32, 4, 2)
// ============================================================
__global__ __launch_bounds__(128) void kernelC(
    const float* __restrict__ asr, const float* __restrict__ mmv)
{
    __shared__ float As[16][64];
    __shared__ float Bs[16][64];

    const int tid = threadIdx.x;
    const int gm = blockIdx.x * 64;
    const int gn = blockIdx.y * 64;
    const int kbase = blockIdx.z * KHALF;
    const int m0 = (tid >> 4) * 8;
    const int n0 = (tid & 15) * 4;

    const int aid0 = tid * 2, aid1 = tid * 2 + 1;
    const int am0 = aid0 >> 2, ak0 = (aid0 & 3) * 4;
    const int am1 = aid1 >> 2, ak1 = (aid1 & 3) * 4;
    const int bk0 = aid0 >> 4, bn0 = (aid0 & 15) * 4;
    const int bk1 = aid1 >> 4, bn1 = (aid1 & 15) * 4;

    ull acc[4][4];
#pragma unroll
    for (int j = 0; j < 4; j++)
#pragma unroll
        for (int i = 0; i < 4; i++) acc[j][i] = 0ull;

    float4 ra0, ra1, rb0, rb1;

#define FETCH(T)                                                                   \
    do {                                                                           \
        int k0 = kbase + (T) * 16;                                                 \
        const float* base; int stride, off;                                        \
        if (k0 < ASR_)        { base = asr; stride = ASR_; off = k0; }             \
        else if (k0 < ZPRE_)  { base = mmv; stride = MM_;  off = k0 - ASR_; }      \
        else                  { base = g_P; stride = F_ * K_; off = k0 - ZPRE_; }  \
        ra0 = *(const float4*)(base + (size_t)(gm + am0) * stride + off + ak0);    \
        ra1 = *(const float4*)(base + (size_t)(gm + am1) * stride + off + ak1);    \
        const float* bb = g_Bmat + (size_t)k0 * OUT_ + gn;                         \
        rb0 = *(const float4*)(bb + (size_t)bk0 * OUT_ + bn0);                     \
        rb1 = *(const float4*)(bb + (size_t)bk1 * OUT_ + bn1);                     \
    } while (0)

#define STASH()                                                                    \
    do {                                                                           \
        As[ak0 + 0][am0] = ra0.x; As[ak0 + 1][am0] = ra0.y;                        \
        As[ak0 + 2][am0] = ra0.z; As[ak0 + 3][am0] = ra0.w;                        \
        As[ak1 + 0][am1] = ra1.x; As[ak1 + 1][am1] = ra1.y;                        \
        As[ak1 + 2][am1] = ra1.z; As[ak1 + 3][am1] = ra1.w;                        \
        *(float4*)&Bs[bk0][bn0] = rb0;                                             \
        *(float4*)&Bs[bk1][bn1] = rb1;                                             \
    } while (0)

    const int T = KHALF / 16;   // 156
    FETCH(0);
    STASH();
    __syncthreads();

    for (int t = 0; t < T; t++) {
        if (t + 1 < T) FETCH(t + 1);
#pragma unroll
        for (int kk = 0; kk < 16; kk++) {
            ull a2[4];
#pragma unroll
            for (int j = 0; j < 4; j++)
                a2[j] = *(const ull*)&As[kk][m0 + 2 * j];
            float4 bv = *(const float4*)&Bs[kk][n0];
            ull bd0 = pack2(bv.x, bv.x), bd1 = pack2(bv.y, bv.y);
            ull bd2 = pack2(bv.z, bv.z), bd3 = pack2(bv.w, bv.w);
#pragma unroll
            for (int j = 0; j < 4; j++) {
                ffma2(acc[j][0], a2[j], bd0);
                ffma2(acc[j][1], a2[j], bd1);
                ffma2(acc[j][2], a2[j], bd2);
                ffma2(acc[j][3], a2[j], bd3);
            }
        }
        __syncthreads();
        if (t + 1 < T) STASH();
        __syncthreads();
    }

    float* outp = g_CP + (size_t)blockIdx.z * (B_ * OUT_);
#pragma unroll
    for (int j = 0; j < 4; j++) {
        const int m = gm + m0 + 2 * j;
#pragma unroll
        for (int i = 0; i < 4; i++) {
            float lo, hi; unpack2(acc[j][i], lo, hi);
            outp[(size_t)m * OUT_ + gn + n0 + i] = lo;
            outp[(size_t)(m + 1) * OUT_ + gn + n0 + i] = hi;
        }
    }
#undef FETCH
#undef STASH
}

// ============================================================
// Kernel D: out = relu(CP[0] + CP[1] + bias)
// grid = 512, 256 threads, float4
// ============================================================
__global__ __launch_bounds__(256) void kernelD(
    const float* __restrict__ pb, float* __restrict__ out)
{
    const int idx = blockIdx.x * 256 + threadIdx.x;   // float4 index, 131072 total
    float4 a = ((const float4*)g_CP)[idx];
    float4 b = ((const float4*)(g_CP + (size_t)B_ * OUT_))[idx];
    float4 bi = ((const float4*)pb)[idx & (OUT_ / 4 - 1)];
    float4 r;
    r.x = fmaxf(a.x + b.x + bi.x, 0.f);
    r.y = fmaxf(a.y + b.y + bi.y, 0.f);
    r.z = fmaxf(a.z + b.z + bi.z, 0.f);
    r.w = fmaxf(a.w + b.w + bi.w, 0.f);
    ((float4*)out)[idx] = r;
}

extern "C" void kernel_launch(void* const* d_in, const int* in_sizes, int n_in,
                              void* d_out, int out_size)
{
    const float* stat = (const float*)d_in[0];
    const float* asr  = (const float*)d_in[1];
    const float* mmv  = (const float*)d_in[2];
    const float* w1   = (const float*)d_in[3];
    const float* b1   = (const float*)d_in[4];
    const float* w2   = (const float*)d_in[5];
    const float* b2   = (const float*)d_in[6];
    const float* tau  = (const float*)d_in[7];
    const float* emb  = (const float*)d_in[8];
    const float* pw   = (const float*)d_in[9];
    const float* pb   = (const float*)d_in[10];
    float* out = (float*)d_out;

    kernelA<<<F_, 256>>>(stat, w1, b1, w2, b2, tau);
    kernelB<<<F_ + ZPRE_ / 32, 256>>>(emb, pw);
    dim3 gc(B_ / 64, OUT_ / 64, 2);
    kernelC<<<gc, 128>>>(asr, mmv);
    kernelD<<<(B_ * OUT_ / 4) / 256, 256>>>(pb, out);
}

// round 4
// speedup vs baseline: 1.6761x; 1.6761x over previous
#include <cuda_runtime.h>
#include <cuda_bf16.h>
#include <cstdint>

// Problem constants
#define B_    2048
#define F_    512
#define H_    64
#define K_    8
#define D_    128
#define ASR_  128
#define MM_   768
#define OUT_  256
#define ZPRE_ (ASR_ + MM_)          // 896
#define ZK_   (ZPRE_ + F_ * K_)     // 4992
#define PROJ_IN_ (ASR_ + MM_ + F_ * D_)   // 66432
#define SPLITK 12
#define KSPLIT (ZK_ / SPLITK)       // 416
#define ITERS  (KSPLIT / 32)        // 13

typedef unsigned long long ull;
typedef uint32_t u32;

// ---------- packed f32x2 helpers ----------
__device__ __forceinline__ ull pack2(float lo, float hi) {
    ull r; asm("mov.b64 %0, {%1, %2};" : "=l"(r) : "f"(lo), "f"(hi)); return r;
}
__device__ __forceinline__ void unpack2(ull v, float& lo, float& hi) {
    asm("mov.b64 {%0, %1}, %2;" : "=f"(lo), "=f"(hi) : "l"(v));
}
__device__ __forceinline__ void ffma2(ull& c, ull a, ull b) {
    asm("fma.rn.f32x2 %0, %1, %2, %0;" : "+l"(c) : "l"(a), "l"(b));
}

__device__ __forceinline__ u32 smem_u32(const void* p) {
    u32 a;
    asm("{ .reg .u64 t; cvta.to.shared.u64 t, %1; cvt.u32.u64 %0, t; }" : "=r"(a) : "l"(p));
    return a;
}

// bf16 split helpers: s[8] floats -> hi uint4 (8 bf16) + lo uint4
__device__ __forceinline__ void split8(const float* s, uint4& h, uint4& l) {
    u32 hh[4], ll[4];
#pragma unroll
    for (int p = 0; p < 4; p++) {
        float2 v = make_float2(s[2 * p], s[2 * p + 1]);
        __nv_bfloat162 hb = __float22bfloat162_rn(v);
        float2 back = __bfloat1622float2(hb);
        __nv_bfloat162 lb = __float22bfloat162_rn(make_float2(v.x - back.x, v.y - back.y));
        hh[p] = *(u32*)&hb;
        ll[p] = *(u32*)&lb;
    }
    h = make_uint4(hh[0], hh[1], hh[2], hh[3]);
    l = make_uint4(ll[0], ll[1], ll[2], ll[3]);
}

// mma.sync m16n8k16 bf16 (compute_80 PTX — compiles at compute_103)
__device__ __forceinline__ void mma_bf16(float* d, const u32* a, const u32* b) {
    asm volatile(
        "mma.sync.aligned.m16n8k16.row.col.f32.bf16.bf16.f32 "
        "{%0,%1,%2,%3}, {%4,%5,%6,%7}, {%8,%9}, {%0,%1,%2,%3};"
        : "+f"(d[0]), "+f"(d[1]), "+f"(d[2]), "+f"(d[3])
        : "r"(a[0]), "r"(a[1]), "r"(a[2]), "r"(a[3]), "r"(b[0]), "r"(b[1]));
}

#define CP_ASYNC(dst, src) \
    asm volatile("cp.async.cg.shared.global [%0], [%1], 16;" :: "r"(dst), "l"(src) : "memory")
#define CP_COMMIT() asm volatile("cp.async.commit_group;" ::: "memory")
#define CP_WAIT(N)  asm volatile("cp.async.wait_group %0;" :: "n"(N) : "memory")

// ---------- device scratch ----------
__device__ __nv_bfloat16 g_Zh[(size_t)B_ * ZK_];   // 20 MB
__device__ __nv_bfloat16 g_Zl[(size_t)B_ * ZK_];
__device__ __nv_bfloat16 g_Bth[(size_t)OUT_ * ZK_];
__device__ __nv_bfloat16 g_Btl[(size_t)OUT_ * ZK_];
__device__ float g_CP[(size_t)SPLITK * B_ * OUT_]; // 25 MB

// ============================================================
// Kernel Z: copy [asr | mm] into Zh/Zl cols 0..895 (bf16 split)
// 896 blocks x 256 thr; thread handles 8 floats.
// ============================================================
__global__ __launch_bounds__(256) void kernelZ(
    const float* __restrict__ asr, const float* __restrict__ mmv)
{
    const int e = blockIdx.x * 256 + threadIdx.x;     // 229376 total
    const int b = e / 112, j8 = e % 112;
    const int col = j8 * 8;
    float s[8];
    if (col < ASR_) {
        const float4* p = (const float4*)(asr + (size_t)b * ASR_ + col);
        float4 v0 = p[0], v1 = p[1];
        s[0]=v0.x; s[1]=v0.y; s[2]=v0.z; s[3]=v0.w;
        s[4]=v1.x; s[5]=v1.y; s[6]=v1.z; s[7]=v1.w;
    } else {
        const float4* p = (const float4*)(mmv + (size_t)b * MM_ + col - ASR_);
        float4 v0 = p[0], v1 = p[1];
        s[0]=v0.x; s[1]=v0.y; s[2]=v0.z; s[3]=v0.w;
        s[4]=v1.x; s[5]=v1.y; s[6]=v1.z; s[7]=v1.w;
    }
    uint4 h, l;
    split8(s, h, l);
    *(uint4*)(g_Zh + (size_t)b * ZK_ + col) = h;
    *(uint4*)(g_Zl + (size_t)b * ZK_ + col) = l;
}

// ============================================================
// Kernel A: sanitize + per-feature MLP + softmax -> Zh/Zl col 896+f*8
// ============================================================
__global__ __launch_bounds__(256) void kernelA(
    const float* __restrict__ stat, const float* __restrict__ w1,
    const float* __restrict__ b1,   const float* __restrict__ w2,
    const float* __restrict__ b2,   const float* __restrict__ tau)
{
    __shared__ float w1s[H_], b1s[H_], b2s[K_], taus[K_];
    __shared__ ull   w2s[H_ * K_ / 2];

    const int f = blockIdx.x;
    const int tid = threadIdx.x;

    if (tid < H_) {
        const float* p = w1 + (size_t)f * 3 * H_;
        w1s[tid] = p[tid] + p[H_ + tid] + p[2 * H_ + tid];
        b1s[tid] = b1[(size_t)f * H_ + tid];
    } else if (tid < H_ + K_) {
        b2s[tid - H_] = b2[(size_t)f * K_ + tid - H_];
        taus[tid - H_] = tau[(size_t)f * K_ + tid - H_];
    }
    if (tid < 128) ((float4*)w2s)[tid] = ((const float4*)(w2 + (size_t)f * H_ * K_))[tid];
    __syncthreads();

    float x[8];
#pragma unroll
    for (int i = 0; i < 8; i++) {
        float v = stat[(size_t)(i * 256 + tid) * F_ + f];
        x[i] = (v >= 0.f) ? v : 0.f;
    }

    ull acc[8][4];
#pragma unroll
    for (int i = 0; i < 8; i++)
#pragma unroll
        for (int k = 0; k < 4; k++) acc[i][k] = 0ull;

#pragma unroll 4
    for (int j = 0; j < H_; j++) {
        const float wj = w1s[j];
        const float bj = b1s[j];
        const ull u0 = w2s[j * 4 + 0];
        const ull u1 = w2s[j * 4 + 1];
        const ull u2 = w2s[j * 4 + 2];
        const ull u3 = w2s[j * 4 + 3];
#pragma unroll
        for (int i = 0; i < 8; i++) {
            float h = fmaf(x[i], wj, bj);
            h = fmaxf(h, 0.01f * h);
            ull h2 = pack2(h, h);
            ffma2(acc[i][0], h2, u0);
            ffma2(acc[i][1], h2, u1);
            ffma2(acc[i][2], h2, u2);
            ffma2(acc[i][3], h2, u3);
        }
    }

#pragma unroll
    for (int i = 0; i < 8; i++) {
        float s[8];
#pragma unroll
        for (int k = 0; k < 4; k++) unpack2(acc[i][k], s[2 * k], s[2 * k + 1]);
        float mx = -3.0e38f;
#pragma unroll
        for (int k = 0; k < K_; k++) {
            float pre = s[k] + b2s[k];
            pre = fmaxf(pre, 0.01f * pre);
            pre *= taus[k];
            s[k] = pre;
            mx = fmaxf(mx, pre);
        }
        float sum = 0.f;
#pragma unroll
        for (int k = 0; k < K_; k++) { s[k] = __expf(s[k] - mx); sum += s[k]; }
        const float inv = __frcp_rn(sum);
#pragma unroll
        for (int k = 0; k < K_; k++) s[k] *= inv;
        uint4 h, l;
        split8(s, h, l);
        const size_t off = (size_t)(i * 256 + tid) * ZK_ + ZPRE_ + f * K_;
        *(uint4*)(g_Zh + off) = h;
        *(uint4*)(g_Zl + off) = l;
    }
}

// ============================================================
// Kernel B: build Bt[256][4992] as bf16 hi/lo.
//   cols 0..895:  proj_w[o][i]
//   col 896+f*8+k: sum_d emb[f,k,d]*proj_w[o,896+f*128+d]
// grid = 512 (M build) + 112 (copy)
// ============================================================
__global__ __launch_bounds__(256) void kernelB(
    const float* __restrict__ emb, const float* __restrict__ pw)
{
    const int blk = blockIdx.x;
    const int tid = threadIdx.x;
    if (blk < F_) {
        __shared__ float es[K_][D_];
        const int f = blk;
        ((float4*)es)[tid] = ((const float4*)(emb + (size_t)f * K_ * D_))[tid];
        __syncthreads();
        const int w = tid >> 5, lid = tid & 31;
        const float* base = pw + ZPRE_ + (size_t)f * D_;
        for (int oi = 0; oi < 32; oi++) {
            const int o = w * 32 + oi;
            float4 wv = *(const float4*)(base + (size_t)o * PROJ_IN_ + lid * 4);
            float acc[K_];
#pragma unroll
            for (int k = 0; k < K_; k++) {
                float4 e4 = *(const float4*)&es[k][lid * 4];
                acc[k] = wv.x * e4.x + wv.y * e4.y + wv.z * e4.z + wv.w * e4.w;
            }
#pragma unroll
            for (int off = 16; off > 0; off >>= 1)
#pragma unroll
                for (int k = 0; k < K_; k++)
                    acc[k] += __shfl_xor_sync(0xffffffff, acc[k], off);
            if (lid == 0) {
                uint4 h, l;
                split8(acc, h, l);
                const size_t doff = (size_t)o * ZK_ + ZPRE_ + f * K_;
                *(uint4*)(g_Bth + doff) = h;
                *(uint4*)(g_Btl + doff) = l;
            }
        }
    } else {
        // copy first 896 cols: 256 rows x 112 j8 = 28672 threads = 112 blocks
        const int e = (blk - F_) * 256 + tid;
        const int o = e / 112, j8 = e % 112;
        const int col = j8 * 8;
        const float4* p = (const float4*)(pw + (size_t)o * PROJ_IN_ + col);
        float4 v0 = p[0], v1 = p[1];
        float s[8] = {v0.x, v0.y, v0.z, v0.w, v1.x, v1.y, v1.z, v1.w};
        uint4 h, l;
        split8(s, h, l);
        *(uint4*)(g_Bth + (size_t)o * ZK_ + col) = h;
        *(uint4*)(g_Btl + (size_t)o * ZK_ + col) = l;
    }
}

// ============================================================
// Kernel C: mma.sync bf16 split-2 GEMM.
// BM=128 BN=128 BK=32, splitK=12, 256 threads (8 warps, 4m x 2n),
// cp.async double buffer, padded SMEM rows (40 bf16 = 80B).
// grid (16, 2, 12)
// ============================================================
#define ROWB 80                        // bytes per padded SMEM row
#define MATB (128 * ROWB)              // 10240 bytes per matrix tile
#define STAGEB (4 * MATB)              // Ah, Al, Bh, Bl
#define SMEM_C_BYTES (2 * STAGEB)      // 81920

__global__ __launch_bounds__(256) void kernelC()
{
    extern __shared__ char smem[];
    const u32 smem_base = smem_u32(smem);
    const int tid = threadIdx.x;
    const int gm = blockIdx.x * 128;
    const int gn = blockIdx.y * 128;
    const int kbase = blockIdx.z * KSPLIT;

    const int lane = tid & 31;
    const int w = tid >> 5;
    const int g = lane >> 2;         // group
    const int tg = lane & 3;         // thread-in-group
    const int m_off = (w & 3) * 32;
    const int n_off = (w >> 2) * 64;

    float d[2][8][4];
#pragma unroll
    for (int i = 0; i < 2; i++)
#pragma unroll
        for (int j = 0; j < 8; j++)
#pragma unroll
            for (int c = 0; c < 4; c++) d[i][j][c] = 0.f;

    // per-thread cp.async mapping: 8 chunks (16B each)
    // chunk c: mat = c>>9 (0:Ah 1:Al 2:Bh 3:Bl), idx=c&511, row=idx>>2, kc=idx&3
#define FETCH(T, S)                                                                  \
    do {                                                                             \
        const int koff = kbase + (T) * 32;                                           \
        _Pragma("unroll")                                                            \
        for (int ci = 0; ci < 8; ci++) {                                             \
            int c = tid + ci * 256;                                                  \
            int mat = c >> 9, idx = c & 511, row = idx >> 2, kc = idx & 3;           \
            const __nv_bfloat16* src;                                                \
            if (mat == 0)      src = g_Zh  + (size_t)(gm + row) * ZK_ + koff + kc*8; \
            else if (mat == 1) src = g_Zl  + (size_t)(gm + row) * ZK_ + koff + kc*8; \
            else if (mat == 2) src = g_Bth + (size_t)(gn + row) * ZK_ + koff + kc*8; \
            else               src = g_Btl + (size_t)(gn + row) * ZK_ + koff + kc*8; \
            u32 dst = smem_base + (S) * STAGEB + mat * MATB + row * ROWB + kc * 16;  \
            CP_ASYNC(dst, src);                                                      \
        }                                                                            \
    } while (0)

    FETCH(0, 0);
    CP_COMMIT();

#pragma unroll 1
    for (int t = 0; t < ITERS; t++) {
        if (t + 1 < ITERS) {
            FETCH(t + 1, (t + 1) & 1);
            CP_COMMIT();
            CP_WAIT(1);
        } else {
            CP_WAIT(0);
        }
        __syncthreads();

        const char* Ah = smem + (t & 1) * STAGEB;
        const char* Al = Ah + MATB;
        const char* Bh = Ah + 2 * MATB;
        const char* Bl = Ah + 3 * MATB;

#pragma unroll
        for (int s16 = 0; s16 < 2; s16++) {
            const int kb = s16 * 32;   // 16 bf16 = 32 bytes
            u32 bh[8][2], bl[8][2];
#pragma unroll
            for (int j = 0; j < 8; j++) {
                int nrow = n_off + j * 8 + g;
                int byte = nrow * ROWB + kb + tg * 4;
                bh[j][0] = *(const u32*)(Bh + byte);
                bh[j][1] = *(const u32*)(Bh + byte + 16);
                bl[j][0] = *(const u32*)(Bl + byte);
                bl[j][1] = *(const u32*)(Bl + byte + 16);
            }
#pragma unroll
            for (int i = 0; i < 2; i++) {
                int rbase = m_off + i * 16 + g;
                int byte = rbase * ROWB + kb + tg * 4;
                u32 ah[4], al[4];
                ah[0] = *(const u32*)(Ah + byte);
                ah[1] = *(const u32*)(Ah + byte + 8 * ROWB);
                ah[2] = *(const u32*)(Ah + byte + 16);
                ah[3] = *(const u32*)(Ah + byte + 8 * ROWB + 16);
                al[0] = *(const u32*)(Al + byte);
                al[1] = *(const u32*)(Al + byte + 8 * ROWB);
                al[2] = *(const u32*)(Al + byte + 16);
                al[3] = *(const u32*)(Al + byte + 8 * ROWB + 16);
#pragma unroll
                for (int j = 0; j < 8; j++) {
                    mma_bf16(d[i][j], ah, bh[j]);   // hi*hi
                    mma_bf16(d[i][j], ah, bl[j]);   // hi*lo
                    mma_bf16(d[i][j], al, bh[j]);   // lo*hi
                }
            }
        }
        __syncthreads();
    }

    // epilogue: write split partial to g_CP
    float* outp = g_CP + (size_t)blockIdx.z * (B_ * OUT_);
#pragma unroll
    for (int i = 0; i < 2; i++) {
        const int row = gm + m_off + 16 * i + g;
#pragma unroll
        for (int j = 0; j < 8; j++) {
            const int col = gn + n_off + 8 * j + 2 * tg;
            *(float2*)(outp + (size_t)row * OUT_ + col)       = make_float2(d[i][j][0], d[i][j][1]);
            *(float2*)(outp + (size_t)(row + 8) * OUT_ + col) = make_float2(d[i][j][2], d[i][j][3]);
        }
    }
#undef FETCH
}

// ============================================================
// Kernel D: out = relu(sum_z CP[z] + bias)
// ============================================================
__global__ __launch_bounds__(256) void kernelD(
    const float* __restrict__ pb, float* __restrict__ out)
{
    const int idx = blockIdx.x * 256 + threadIdx.x;   // f4 index, 131072 total
    float4 a = make_float4(0.f, 0.f, 0.f, 0.f);
#pragma unroll
    for (int z = 0; z < SPLITK; z++) {
        float4 v = ((const float4*)g_CP)[(size_t)z * (B_ * OUT_ / 4) + idx];
        a.x += v.x; a.y += v.y; a.z += v.z; a.w += v.w;
    }
    float4 bi = ((const float4*)pb)[idx & (OUT_ / 4 - 1)];
    float4 r;
    r.x = fmaxf(a.x + bi.x, 0.f);
    r.y = fmaxf(a.y + bi.y, 0.f);
    r.z = fmaxf(a.z + bi.z, 0.f);
    r.w = fmaxf(a.w + bi.w, 0.f);
    ((float4*)out)[idx] = r;
}

extern "C" void kernel_launch(void* const* d_in, const int* in_sizes, int n_in,
                              void* d_out, int out_size)
{
    const float* stat = (const float*)d_in[0];
    const float* asr  = (const float*)d_in[1];
    const float* mmv  = (const float*)d_in[2];
    const float* w1   = (const float*)d_in[3];
    const float* b1   = (const float*)d_in[4];
    const float* w2   = (const float*)d_in[5];
    const float* b2   = (const float*)d_in[6];
    const float* tau  = (const float*)d_in[7];
    const float* emb  = (const float*)d_in[8];
    const float* pw   = (const float*)d_in[9];
    const float* pb   = (const float*)d_in[10];
    float* out = (float*)d_out;

    static int smem_set = 0;
    if (!smem_set) {
        cudaFuncSetAttribute(kernelC, cudaFuncAttributeMaxDynamicSharedMemorySize, SMEM_C_BYTES);
        smem_set = 1;
    }

    kernelZ<<<896, 256>>>(asr, mmv);
    kernelA<<<F_, 256>>>(stat, w1, b1, w2, b2, tau);
    kernelB<<<F_ + 112, 256>>>(emb, pw);
    dim3 gc(B_ / 128, OUT_ / 128, SPLITK);
    kernelC<<<gc, 256, SMEM_C_BYTES>>>();
    kernelD<<<(B_ * OUT_ / 4) / 256, 256>>>(pb, out);
}